// round 8
// baseline (speedup 1.0000x reference)
#include <cuda_runtime.h>
#include <cuda_bf16.h>
#include <math.h>
#include <stdint.h>

#define BSZ 2
#define TSZ 2048
#define DSZ 512
#define HSZ 8
#define CSZ 64
#define WINSZ 128
#define MROWS (BSZ*TSZ)   // 4096
#define KEXP 1536          // 3 * 512 (bf16 split: hi | lo | hi)
#define NCH 48             // KEXP / 32
#define LDT 40             // padded smem row stride (bf16 elems)

// ---------------------------------------------------------------------------
// Scratch (device globals: no allocation allowed)
// ---------------------------------------------------------------------------
__device__ float g_q[BSZ*TSZ*HSZ*CSZ];
__device__ float g_k[BSZ*TSZ*HSZ*CSZ];
__device__ float g_v[BSZ*TSZ*HSZ*CSZ];
__device__ __nv_bfloat16 g_Abf[MROWS*KEXP];     // split h
__device__ __nv_bfloat16 g_attbf[MROWS*KEXP];   // split attention output
__device__ __nv_bfloat16 g_Wqb[512*KEXP];
__device__ __nv_bfloat16 g_Wkb[512*KEXP];
__device__ __nv_bfloat16 g_Wvb[512*KEXP];
__device__ __nv_bfloat16 g_Wob[512*KEXP];

// ---------------------------------------------------------------------------
// mma.sync helpers (sm_80+ PTX — compiles on base sm_103 target)
// ---------------------------------------------------------------------------
__device__ __forceinline__ uint32_t smem_u32(const void* p) {
    uint32_t a;
    asm("{ .reg .u64 t; cvta.to.shared.u64 t, %1; cvt.u32.u64 %0, t; }" : "=r"(a) : "l"(p));
    return a;
}
__device__ __forceinline__ void ldm_x4(uint32_t& r0, uint32_t& r1,
                                       uint32_t& r2, uint32_t& r3, uint32_t addr) {
    asm volatile("ldmatrix.sync.aligned.m8n8.x4.shared.b16 {%0,%1,%2,%3}, [%4];"
                 : "=r"(r0), "=r"(r1), "=r"(r2), "=r"(r3) : "r"(addr));
}
__device__ __forceinline__ void mma16816(float* d, const uint32_t* a, const uint32_t* b) {
    asm volatile("mma.sync.aligned.m16n8k16.row.col.f32.bf16.bf16.f32 "
                 "{%0,%1,%2,%3}, {%4,%5,%6,%7}, {%8,%9}, {%0,%1,%2,%3};"
                 : "+f"(d[0]), "+f"(d[1]), "+f"(d[2]), "+f"(d[3])
                 : "r"(a[0]), "r"(a[1]), "r"(a[2]), "r"(a[3]), "r"(b[0]), "r"(b[1]));
}

// ---------------------------------------------------------------------------
// Split conversions: x -> (hi, lo, hi) / weights -> transposed (hi, hi, lo)
// ---------------------------------------------------------------------------
__global__ void __launch_bounds__(256)
convert_h(const float* __restrict__ h)
{
    int idx = blockIdx.x * 256 + threadIdx.x;       // 0 .. 4096*512-1
    int m = idx >> 9, k = idx & 511;
    float x = h[idx];
    __nv_bfloat16 hi = __float2bfloat16(x);
    __nv_bfloat16 lo = __float2bfloat16(x - __bfloat162float(hi));
    size_t base = (size_t)m * KEXP;
    g_Abf[base + k]        = hi;
    g_Abf[base + 512 + k]  = lo;
    g_Abf[base + 1024 + k] = hi;
}

__global__ void __launch_bounds__(256)
convert_w(const float* __restrict__ Wq, const float* __restrict__ Wk,
          const float* __restrict__ Wv, const float* __restrict__ Wo)
{
    const float* W = (blockIdx.z == 0) ? Wq : (blockIdx.z == 1) ? Wk
                   : (blockIdx.z == 2) ? Wv : Wo;
    __nv_bfloat16* Wb = (blockIdx.z == 0) ? g_Wqb : (blockIdx.z == 1) ? g_Wkb
                      : (blockIdx.z == 2) ? g_Wvb : g_Wob;
    int idx = blockIdx.x * 256 + threadIdx.x;       // 0 .. 512*512-1
    int k = idx >> 9, n = idx & 511;                 // W[k][n]
    float x = W[idx];
    __nv_bfloat16 hi = __float2bfloat16(x);
    __nv_bfloat16 lo = __float2bfloat16(x - __bfloat162float(hi));
    size_t base = (size_t)n * KEXP;
    Wb[base + k]        = hi;
    Wb[base + 512 + k]  = hi;
    Wb[base + 1024 + k] = lo;
}

// ---------------------------------------------------------------------------
// bf16 mma.sync GEMM: C[128x128 tile] = A'[M,1536] @ B'[N,1536]^T, fp32 accum.
// 256 threads = 8 warps (4 along M x 2 along N); warp tile 32x64.
// K-chunk 32, double-buffered smem, reg-staged prefetch.
// ---------------------------------------------------------------------------
__device__ __forceinline__ void gemm_mma_body(const __nv_bfloat16* __restrict__ A,
                                              const __nv_bfloat16* __restrict__ Bw,
                                              float* __restrict__ C)
{
    __shared__ __nv_bfloat16 As[2][128 * LDT];
    __shared__ __nv_bfloat16 Bs[2][128 * LDT];

    const int tid = threadIdx.x;
    const int lane = tid & 31, wid = tid >> 5;
    const int wm = (wid & 3) * 32;      // warp M offset
    const int wn = (wid >> 2) * 64;     // warp N offset
    const int m0 = blockIdx.y * 128, n0 = blockIdx.x * 128;

    // load mapping: each thread stages rows lrow and lrow+64, 8 bf16 at lseg
    const int lrow = tid >> 2;
    const int lseg = (tid & 3) * 8;
    const __nv_bfloat16* gA = A  + (size_t)(m0 + lrow) * KEXP + lseg;
    const __nv_bfloat16* gB = Bw + (size_t)(n0 + lrow) * KEXP + lseg;
    const int soff  = lrow * LDT + lseg;
    const int soff2 = (lrow + 64) * LDT + lseg;

    float acc[2][8][4];
#pragma unroll
    for (int mt = 0; mt < 2; mt++)
#pragma unroll
        for (int nt = 0; nt < 8; nt++)
#pragma unroll
            for (int r = 0; r < 4; r++) acc[mt][nt][r] = 0.f;

    uint4 ra0, ra1, rb0, rb1;
    // prologue: chunk 0
    ra0 = *(const uint4*)(gA);
    ra1 = *(const uint4*)(gA + (size_t)64 * KEXP);
    rb0 = *(const uint4*)(gB);
    rb1 = *(const uint4*)(gB + (size_t)64 * KEXP);
    *(uint4*)&As[0][soff]  = ra0;
    *(uint4*)&As[0][soff2] = ra1;
    *(uint4*)&Bs[0][soff]  = rb0;
    *(uint4*)&Bs[0][soff2] = rb1;
    __syncthreads();

    const int a_ld = (wm + (lane & 15)) * LDT + (lane >> 4) * 8;
    const int b_ld = (wn + (lane & 15)) * LDT + (lane >> 4) * 8;

    for (int c = 0; c < NCH; c++) {
        const int buf = c & 1;
        if (c + 1 < NCH) {
            const int k0 = (c + 1) * 32;
            ra0 = *(const uint4*)(gA + k0);
            ra1 = *(const uint4*)(gA + (size_t)64 * KEXP + k0);
            rb0 = *(const uint4*)(gB + k0);
            rb1 = *(const uint4*)(gB + (size_t)64 * KEXP + k0);
        }

        const uint32_t sa = smem_u32(&As[buf][0]);
        const uint32_t sb = smem_u32(&Bs[buf][0]);
#pragma unroll
        for (int ks = 0; ks < 2; ks++) {
            const int kk = ks * 16;
            uint32_t a[2][4];
#pragma unroll
            for (int mt = 0; mt < 2; mt++)
                ldm_x4(a[mt][0], a[mt][1], a[mt][2], a[mt][3],
                       sa + 2 * (a_ld + mt * 16 * LDT + kk));
            uint32_t b[8][2];
#pragma unroll
            for (int np = 0; np < 4; np++) {
                uint32_t r0, r1, r2, r3;
                ldm_x4(r0, r1, r2, r3, sb + 2 * (b_ld + np * 16 * LDT + kk));
                b[2*np][0] = r0; b[2*np][1] = r2;
                b[2*np+1][0] = r1; b[2*np+1][1] = r3;
            }
#pragma unroll
            for (int mt = 0; mt < 2; mt++)
#pragma unroll
                for (int nt = 0; nt < 8; nt++)
                    mma16816(acc[mt][nt], a[mt], b[nt]);
        }
        __syncthreads();
        if (c + 1 < NCH) {
            const int nb = 1 - buf;
            *(uint4*)&As[nb][soff]  = ra0;
            *(uint4*)&As[nb][soff2] = ra1;
            *(uint4*)&Bs[nb][soff]  = rb0;
            *(uint4*)&Bs[nb][soff2] = rb1;
            __syncthreads();
        }
    }

    // epilogue: fragment -> global (row stride 512)
    const int gr = lane >> 2, gc = (lane & 3) * 2;
#pragma unroll
    for (int mt = 0; mt < 2; mt++)
#pragma unroll
        for (int nt = 0; nt < 8; nt++) {
            float* base = C + (size_t)(m0 + wm + mt * 16 + gr) * 512 + n0 + wn + nt * 8 + gc;
            *(float2*)base             = make_float2(acc[mt][nt][0], acc[mt][nt][1]);
            *(float2*)(base + 8 * 512) = make_float2(acc[mt][nt][2], acc[mt][nt][3]);
        }
}

__global__ void __launch_bounds__(256)
qkv_mma()
{
    const __nv_bfloat16* B = (blockIdx.z == 0) ? g_Wqb : (blockIdx.z == 1) ? g_Wkb : g_Wvb;
    float* C = (blockIdx.z == 0) ? g_q : (blockIdx.z == 1) ? g_k : g_v;
    gemm_mma_body(g_Abf, B, C);
}

__global__ void __launch_bounds__(256)
out_mma(float* __restrict__ out)
{
    gemm_mma_body(g_attbf, g_Wob, out);
}

// ---------------------------------------------------------------------------
// RMSNorm + RoPE (fp32 in place on g_q / g_k)
// ---------------------------------------------------------------------------
__global__ void __launch_bounds__(256)
norm_rope(const float* __restrict__ cosT, const float* __restrict__ sinT,
          const float* __restrict__ qw, const float* __restrict__ kw)
{
    int w = blockIdx.x * 8 + (threadIdx.x >> 5);
    int lane = threadIdx.x & 31;
    int t = (w / HSZ) % TSZ;

    float* x = ((blockIdx.y == 0) ? g_q : g_k) + (size_t)w * CSZ;
    const float* wgt = (blockIdx.y == 0) ? qw : kw;

    float x0 = x[lane];
    float x1 = x[lane + 32];
    float ss = x0 * x0 + x1 * x1;
#pragma unroll
    for (int o = 16; o; o >>= 1) ss += __shfl_xor_sync(0xffffffffu, ss, o);
    float nrm = rsqrtf(ss * (1.f / CSZ) + 1e-6f);
    float y0 = x0 * nrm * wgt[lane];
    float y1 = x1 * nrm * wgt[lane + 32];

    float c0 = cosT[t * CSZ + lane];
    float c1 = cosT[t * CSZ + lane + 32];
    float s0 = sinT[t * CSZ + lane];
    float s1 = sinT[t * CSZ + lane + 32];
    x[lane]      = y0 * c0 - y1 * s0;
    x[lane + 32] = y1 * c1 + y0 * s1;
}

// ---------------------------------------------------------------------------
// Sliding-window attention; epilogue writes bf16 split directly into g_attbf.
// ---------------------------------------------------------------------------
__global__ void __launch_bounds__(256)
attn_kernel()
{
    __shared__ float Qs[32][65];
    __shared__ float Ks[64][65];
    __shared__ float Vs[64][65];

    const int b = blockIdx.z, h = blockIdx.y;
    const int t0 = blockIdx.x * 32;
    const int tid = threadIdx.x;
    const int lane = tid & 31;
    const int w = tid >> 5;

    for (int idx = tid; idx < 32 * 16; idx += 256) {
        int r = idx >> 4, c4 = (idx & 15) * 4;
        float4 v = *(const float4*)&g_q[(((size_t)(b * TSZ + t0 + r) * HSZ) + h) * CSZ + c4];
        Qs[r][c4 + 0] = v.x; Qs[r][c4 + 1] = v.y; Qs[r][c4 + 2] = v.z; Qs[r][c4 + 3] = v.w;
    }

    float m[4], l[4], o0[4], o1[4];
#pragma unroll
    for (int q = 0; q < 4; q++) { m[q] = -INFINITY; l[q] = 0.f; o0[q] = 0.f; o1[q] = 0.f; }

    for (int ch = 0; ch < 3; ch++) {
        int s_base = t0 - 128 + ch * 64;
        for (int idx = tid; idx < 64 * 16; idx += 256) {
            int r = idx >> 4, c4 = (idx & 15) * 4;
            int s = s_base + r;
            float4 kv = make_float4(0.f, 0.f, 0.f, 0.f), vv = kv;
            if (s >= 0 && s < TSZ) {
                size_t base = (((size_t)(b * TSZ + s) * HSZ) + h) * CSZ + c4;
                kv = *(const float4*)&g_k[base];
                vv = *(const float4*)&g_v[base];
            }
            Ks[r][c4 + 0] = kv.x; Ks[r][c4 + 1] = kv.y; Ks[r][c4 + 2] = kv.z; Ks[r][c4 + 3] = kv.w;
            Vs[r][c4 + 0] = vv.x; Vs[r][c4 + 1] = vv.y; Vs[r][c4 + 2] = vv.z; Vs[r][c4 + 3] = vv.w;
        }
        __syncthreads();

#pragma unroll
        for (int q = 0; q < 4; q++) {
            const int qi = w * 4 + q;
            const int i = t0 + qi;
            float acc0 = 0.f, acc1 = 0.f;
#pragma unroll
            for (int c = 0; c < 64; c++) {
                float qv = Qs[qi][c];
                acc0 = fmaf(qv, Ks[lane][c], acc0);
                acc1 = fmaf(qv, Ks[lane + 32][c], acc1);
            }
            int s0g = s_base + lane, s1g = s_base + lane + 32;
            float l0 = (s0g >= 0 && s0g <= i && s0g > i - WINSZ) ? acc0 * 0.125f : -INFINITY;
            float l1 = (s1g >= 0 && s1g <= i && s1g > i - WINSZ) ? acc1 * 0.125f : -INFINITY;
            float cm = fmaxf(l0, l1);
#pragma unroll
            for (int o = 16; o; o >>= 1) cm = fmaxf(cm, __shfl_xor_sync(0xffffffffu, cm, o));
            float mn = fmaxf(m[q], cm);
            if (mn == -INFINITY) continue;

            float scale = expf(m[q] - mn);
            float p0 = expf(l0 - mn);
            float p1 = expf(l1 - mn);
            float psum = p0 + p1;
#pragma unroll
            for (int o = 16; o; o >>= 1) psum += __shfl_xor_sync(0xffffffffu, psum, o);
            l[q] = l[q] * scale + psum;
            o0[q] *= scale;
            o1[q] *= scale;
#pragma unroll
            for (int s2 = 0; s2 < 32; s2++) {
                float p = __shfl_sync(0xffffffffu, p0, s2);
                o0[q] = fmaf(p, Vs[s2][lane], o0[q]);
                o1[q] = fmaf(p, Vs[s2][lane + 32], o1[q]);
            }
#pragma unroll
            for (int s2 = 0; s2 < 32; s2++) {
                float p = __shfl_sync(0xffffffffu, p1, s2);
                o0[q] = fmaf(p, Vs[s2 + 32][lane], o0[q]);
                o1[q] = fmaf(p, Vs[s2 + 32][lane + 32], o1[q]);
            }
            m[q] = mn;
        }
        __syncthreads();
    }

#pragma unroll
    for (int q = 0; q < 4; q++) {
        int i = t0 + w * 4 + q;
        float inv = 1.f / l[q];
        float v0 = o0[q] * inv, v1 = o1[q] * inv;
        size_t base = (size_t)(b * TSZ + i) * KEXP + h * CSZ;
        __nv_bfloat16 h0 = __float2bfloat16(v0);
        __nv_bfloat16 lo0 = __float2bfloat16(v0 - __bfloat162float(h0));
        __nv_bfloat16 h1 = __float2bfloat16(v1);
        __nv_bfloat16 lo1 = __float2bfloat16(v1 - __bfloat162float(h1));
        g_attbf[base + lane]              = h0;
        g_attbf[base + 512 + lane]        = lo0;
        g_attbf[base + 1024 + lane]       = h0;
        g_attbf[base + lane + 32]         = h1;
        g_attbf[base + 512 + lane + 32]   = lo1;
        g_attbf[base + 1024 + lane + 32]  = h1;
    }
}

// ---------------------------------------------------------------------------
extern "C" void kernel_launch(void* const* d_in, const int* in_sizes, int n_in,
                              void* d_out, int out_size)
{
    const float* h        = (const float*)d_in[0];
    const float* rope_cos = (const float*)d_in[1];
    const float* rope_sin = (const float*)d_in[2];
    const float* W_q      = (const float*)d_in[3];
    const float* W_k      = (const float*)d_in[4];
    const float* W_v      = (const float*)d_in[5];
    const float* W_o      = (const float*)d_in[6];
    const float* q_norm_w = (const float*)d_in[7];
    const float* k_norm_w = (const float*)d_in[8];
    float* out = (float*)d_out;

    convert_h<<<(MROWS * DSZ) / 256, 256>>>(h);
    convert_w<<<dim3((512 * 512) / 256, 1, 4), 256>>>(W_q, W_k, W_v, W_o);

    qkv_mma<<<dim3(4, 32, 3), 256>>>();

    norm_rope<<<dim3(BSZ * TSZ * HSZ / 8, 2), 256>>>(rope_cos, rope_sin, q_norm_w, k_norm_w);

    attn_kernel<<<dim3(TSZ / 32, HSZ, BSZ), 256>>>();

    out_mma<<<dim3(4, 32, 1), 256>>>(out);
}

// round 9
// speedup vs baseline: 1.6443x; 1.6443x over previous
#include <cuda_runtime.h>
#include <cuda_bf16.h>
#include <math.h>
#include <stdint.h>

#define BSZ 2
#define TSZ 2048
#define DSZ 512
#define HSZ 8
#define CSZ 64
#define WINSZ 128
#define MROWS (BSZ*TSZ)   // 4096
#define KEXP 1536          // 3 * 512 (bf16 split: hi | lo | hi)
#define KC 64              // K per pipeline chunk
#define NCH (KEXP/KC)      // 24
#define STAGES 3
#define LDT 72             // padded smem row stride (bf16 elems); 144B rows
#define STAGE_ELEMS (128*LDT)              // 9216
#define SMEM_BYTES (2*STAGES*STAGE_ELEMS*2) // 110592

// ---------------------------------------------------------------------------
// Scratch (device globals: no allocation allowed)
// ---------------------------------------------------------------------------
__device__ float g_q[BSZ*TSZ*HSZ*CSZ];
__device__ float g_k[BSZ*TSZ*HSZ*CSZ];
__device__ float g_v[BSZ*TSZ*HSZ*CSZ];
__device__ __nv_bfloat16 g_Abf[MROWS*KEXP];     // split h
__device__ __nv_bfloat16 g_attbf[MROWS*KEXP];   // split attention output
__device__ __nv_bfloat16 g_Wqb[512*KEXP];
__device__ __nv_bfloat16 g_Wkb[512*KEXP];
__device__ __nv_bfloat16 g_Wvb[512*KEXP];
__device__ __nv_bfloat16 g_Wob[512*KEXP];

// ---------------------------------------------------------------------------
// PTX helpers (sm_80+ — compile on base sm_103 target)
// ---------------------------------------------------------------------------
__device__ __forceinline__ uint32_t smem_u32(const void* p) {
    uint32_t a;
    asm("{ .reg .u64 t; cvta.to.shared.u64 t, %1; cvt.u32.u64 %0, t; }" : "=r"(a) : "l"(p));
    return a;
}
__device__ __forceinline__ void cp16(uint32_t dst, const void* src) {
    asm volatile("cp.async.cg.shared.global [%0], [%1], 16;" :: "r"(dst), "l"(src));
}
#define CP_COMMIT() asm volatile("cp.async.commit_group;" ::: "memory")
#define CP_WAIT(n)  asm volatile("cp.async.wait_group %0;" :: "n"(n) : "memory")

__device__ __forceinline__ void ldm_x4(uint32_t& r0, uint32_t& r1,
                                       uint32_t& r2, uint32_t& r3, uint32_t addr) {
    asm volatile("ldmatrix.sync.aligned.m8n8.x4.shared.b16 {%0,%1,%2,%3}, [%4];"
                 : "=r"(r0), "=r"(r1), "=r"(r2), "=r"(r3) : "r"(addr));
}
__device__ __forceinline__ void mma16816(float* d, const uint32_t* a, const uint32_t* b) {
    asm volatile("mma.sync.aligned.m16n8k16.row.col.f32.bf16.bf16.f32 "
                 "{%0,%1,%2,%3}, {%4,%5,%6,%7}, {%8,%9}, {%0,%1,%2,%3};"
                 : "+f"(d[0]), "+f"(d[1]), "+f"(d[2]), "+f"(d[3])
                 : "r"(a[0]), "r"(a[1]), "r"(a[2]), "r"(a[3]), "r"(b[0]), "r"(b[1]));
}

// ---------------------------------------------------------------------------
// Split conversions: x -> (hi, lo, hi) / weights -> transposed (hi, hi, lo)
// ---------------------------------------------------------------------------
__global__ void __launch_bounds__(256)
convert_h(const float* __restrict__ h)
{
    int idx = blockIdx.x * 256 + threadIdx.x;       // 0 .. 4096*512-1
    int m = idx >> 9, k = idx & 511;
    float x = h[idx];
    __nv_bfloat16 hi = __float2bfloat16(x);
    __nv_bfloat16 lo = __float2bfloat16(x - __bfloat162float(hi));
    size_t base = (size_t)m * KEXP;
    g_Abf[base + k]        = hi;
    g_Abf[base + 512 + k]  = lo;
    g_Abf[base + 1024 + k] = hi;
}

__global__ void __launch_bounds__(256)
convert_w(const float* __restrict__ Wq, const float* __restrict__ Wk,
          const float* __restrict__ Wv, const float* __restrict__ Wo)
{
    const float* W = (blockIdx.z == 0) ? Wq : (blockIdx.z == 1) ? Wk
                   : (blockIdx.z == 2) ? Wv : Wo;
    __nv_bfloat16* Wb = (blockIdx.z == 0) ? g_Wqb : (blockIdx.z == 1) ? g_Wkb
                      : (blockIdx.z == 2) ? g_Wvb : g_Wob;
    int idx = blockIdx.x * 256 + threadIdx.x;       // 0 .. 512*512-1
    int k = idx >> 9, n = idx & 511;                 // W[k][n]
    float x = W[idx];
    __nv_bfloat16 hi = __float2bfloat16(x);
    __nv_bfloat16 lo = __float2bfloat16(x - __bfloat162float(hi));
    size_t base = (size_t)n * KEXP;
    Wb[base + k]        = hi;
    Wb[base + 512 + k]  = hi;
    Wb[base + 1024 + k] = lo;
}

// ---------------------------------------------------------------------------
// bf16 mma.sync GEMM with cp.async 3-stage pipeline.
// C[128x128 tile] = A'[M,1536] @ B'[N,1536]^T, fp32 accum.
// 256 threads = 8 warps (4 along M x 2 along N); warp tile 32x64.
// ---------------------------------------------------------------------------
__device__ __forceinline__ void gemm_mma_body(const __nv_bfloat16* __restrict__ A,
                                              const __nv_bfloat16* __restrict__ Bw,
                                              float* __restrict__ C,
                                              __nv_bfloat16* sm)
{
    const int tid = threadIdx.x;
    const int lane = tid & 31, wid = tid >> 5;
    const int wm = (wid & 3) * 32;      // warp M offset
    const int wn = (wid >> 2) * 64;     // warp N offset
    const int m0 = blockIdx.y * 128, n0 = blockIdx.x * 128;

    const uint32_t smA = smem_u32(sm);
    const uint32_t smB = smA + STAGES * STAGE_ELEMS * 2;

    // cp.async mapping: 1024 16B-units per matrix per stage; 4 per thread.
    // unit u: row = u>>3 (8 units/row of KC=64 elems), seg = (u&7)*8 elems.
    const __nv_bfloat16* gA = A  + (size_t)m0 * KEXP;
    const __nv_bfloat16* gB = Bw + (size_t)n0 * KEXP;

    auto load_stage = [&](int s, int c) {
        const int k0 = c * KC;
        const uint32_t dA = smA + s * STAGE_ELEMS * 2;
        const uint32_t dB = smB + s * STAGE_ELEMS * 2;
#pragma unroll
        for (int i = 0; i < 4; i++) {
            int u = i * 256 + tid;
            int row = u >> 3, seg = (u & 7) * 8;
            uint32_t so = (uint32_t)(row * LDT + seg) * 2;
            cp16(dA + so, gA + (size_t)row * KEXP + k0 + seg);
            cp16(dB + so, gB + (size_t)row * KEXP + k0 + seg);
        }
    };

    float acc[2][8][4];
#pragma unroll
    for (int mt = 0; mt < 2; mt++)
#pragma unroll
        for (int nt = 0; nt < 8; nt++)
#pragma unroll
            for (int r = 0; r < 4; r++) acc[mt][nt][r] = 0.f;

    // prologue: stages 0..STAGES-2
    load_stage(0, 0); CP_COMMIT();
    load_stage(1, 1); CP_COMMIT();

    const int a_ld = (wm + (lane & 15)) * LDT + (lane >> 4) * 8;
    const int b_ld = (wn + (lane & 15)) * LDT + (lane >> 4) * 8;

    for (int c = 0; c < NCH; c++) {
        CP_WAIT(STAGES - 2);
        __syncthreads();

        // issue next stage before compute (overlaps global latency with MMA)
        if (c + STAGES - 1 < NCH) load_stage((c + STAGES - 1) % STAGES, c + STAGES - 1);
        CP_COMMIT();

        const int buf = c % STAGES;
        const uint32_t sa = smA + buf * STAGE_ELEMS * 2;
        const uint32_t sb = smB + buf * STAGE_ELEMS * 2;
#pragma unroll
        for (int ks = 0; ks < 4; ks++) {
            const int kk = ks * 16;
            uint32_t a[2][4];
#pragma unroll
            for (int mt = 0; mt < 2; mt++)
                ldm_x4(a[mt][0], a[mt][1], a[mt][2], a[mt][3],
                       sa + 2 * (a_ld + mt * 16 * LDT + kk));
            uint32_t b[8][2];
#pragma unroll
            for (int np = 0; np < 4; np++) {
                uint32_t r0, r1, r2, r3;
                ldm_x4(r0, r1, r2, r3, sb + 2 * (b_ld + np * 16 * LDT + kk));
                b[2*np][0] = r0; b[2*np][1] = r2;
                b[2*np+1][0] = r1; b[2*np+1][1] = r3;
            }
#pragma unroll
            for (int mt = 0; mt < 2; mt++)
#pragma unroll
                for (int nt = 0; nt < 8; nt++)
                    mma16816(acc[mt][nt], a[mt], b[nt]);
        }
    }

    // epilogue: fragment -> global (row stride 512)
    const int gr = lane >> 2, gc = (lane & 3) * 2;
#pragma unroll
    for (int mt = 0; mt < 2; mt++)
#pragma unroll
        for (int nt = 0; nt < 8; nt++) {
            float* base = C + (size_t)(m0 + wm + mt * 16 + gr) * 512 + n0 + wn + nt * 8 + gc;
            *(float2*)base             = make_float2(acc[mt][nt][0], acc[mt][nt][1]);
            *(float2*)(base + 8 * 512) = make_float2(acc[mt][nt][2], acc[mt][nt][3]);
        }
}

__global__ void __launch_bounds__(256)
qkv_mma()
{
    extern __shared__ __nv_bfloat16 sm[];
    const __nv_bfloat16* B = (blockIdx.z == 0) ? g_Wqb : (blockIdx.z == 1) ? g_Wkb : g_Wvb;
    float* C = (blockIdx.z == 0) ? g_q : (blockIdx.z == 1) ? g_k : g_v;
    gemm_mma_body(g_Abf, B, C, sm);
}

__global__ void __launch_bounds__(256)
out_mma(float* __restrict__ out)
{
    extern __shared__ __nv_bfloat16 sm[];
    gemm_mma_body(g_attbf, g_Wob, out, sm);
}

// ---------------------------------------------------------------------------
// RMSNorm + RoPE (fp32 in place on g_q / g_k)
// ---------------------------------------------------------------------------
__global__ void __launch_bounds__(256)
norm_rope(const float* __restrict__ cosT, const float* __restrict__ sinT,
          const float* __restrict__ qw, const float* __restrict__ kw)
{
    int w = blockIdx.x * 8 + (threadIdx.x >> 5);
    int lane = threadIdx.x & 31;
    int t = (w / HSZ) % TSZ;

    float* x = ((blockIdx.y == 0) ? g_q : g_k) + (size_t)w * CSZ;
    const float* wgt = (blockIdx.y == 0) ? qw : kw;

    float x0 = x[lane];
    float x1 = x[lane + 32];
    float ss = x0 * x0 + x1 * x1;
#pragma unroll
    for (int o = 16; o; o >>= 1) ss += __shfl_xor_sync(0xffffffffu, ss, o);
    float nrm = rsqrtf(ss * (1.f / CSZ) + 1e-6f);
    float y0 = x0 * nrm * wgt[lane];
    float y1 = x1 * nrm * wgt[lane + 32];

    float c0 = cosT[t * CSZ + lane];
    float c1 = cosT[t * CSZ + lane + 32];
    float s0 = sinT[t * CSZ + lane];
    float s1 = sinT[t * CSZ + lane + 32];
    x[lane]      = y0 * c0 - y1 * s0;
    x[lane + 32] = y1 * c1 + y0 * s1;
}

// ---------------------------------------------------------------------------
// Sliding-window attention; epilogue writes bf16 split directly into g_attbf.
// ---------------------------------------------------------------------------
__global__ void __launch_bounds__(256)
attn_kernel()
{
    __shared__ float Qs[32][65];
    __shared__ float Ks[64][65];
    __shared__ float Vs[64][65];

    const int b = blockIdx.z, h = blockIdx.y;
    const int t0 = blockIdx.x * 32;
    const int tid = threadIdx.x;
    const int lane = tid & 31;
    const int w = tid >> 5;

    for (int idx = tid; idx < 32 * 16; idx += 256) {
        int r = idx >> 4, c4 = (idx & 15) * 4;
        float4 v = *(const float4*)&g_q[(((size_t)(b * TSZ + t0 + r) * HSZ) + h) * CSZ + c4];
        Qs[r][c4 + 0] = v.x; Qs[r][c4 + 1] = v.y; Qs[r][c4 + 2] = v.z; Qs[r][c4 + 3] = v.w;
    }

    float m[4], l[4], o0[4], o1[4];
#pragma unroll
    for (int q = 0; q < 4; q++) { m[q] = -INFINITY; l[q] = 0.f; o0[q] = 0.f; o1[q] = 0.f; }

    for (int ch = 0; ch < 3; ch++) {
        int s_base = t0 - 128 + ch * 64;
        for (int idx = tid; idx < 64 * 16; idx += 256) {
            int r = idx >> 4, c4 = (idx & 15) * 4;
            int s = s_base + r;
            float4 kv = make_float4(0.f, 0.f, 0.f, 0.f), vv = kv;
            if (s >= 0 && s < TSZ) {
                size_t base = (((size_t)(b * TSZ + s) * HSZ) + h) * CSZ + c4;
                kv = *(const float4*)&g_k[base];
                vv = *(const float4*)&g_v[base];
            }
            Ks[r][c4 + 0] = kv.x; Ks[r][c4 + 1] = kv.y; Ks[r][c4 + 2] = kv.z; Ks[r][c4 + 3] = kv.w;
            Vs[r][c4 + 0] = vv.x; Vs[r][c4 + 1] = vv.y; Vs[r][c4 + 2] = vv.z; Vs[r][c4 + 3] = vv.w;
        }
        __syncthreads();

#pragma unroll
        for (int q = 0; q < 4; q++) {
            const int qi = w * 4 + q;
            const int i = t0 + qi;
            float acc0 = 0.f, acc1 = 0.f;
#pragma unroll
            for (int c = 0; c < 64; c++) {
                float qv = Qs[qi][c];
                acc0 = fmaf(qv, Ks[lane][c], acc0);
                acc1 = fmaf(qv, Ks[lane + 32][c], acc1);
            }
            int s0g = s_base + lane, s1g = s_base + lane + 32;
            float l0 = (s0g >= 0 && s0g <= i && s0g > i - WINSZ) ? acc0 * 0.125f : -INFINITY;
            float l1 = (s1g >= 0 && s1g <= i && s1g > i - WINSZ) ? acc1 * 0.125f : -INFINITY;
            float cm = fmaxf(l0, l1);
#pragma unroll
            for (int o = 16; o; o >>= 1) cm = fmaxf(cm, __shfl_xor_sync(0xffffffffu, cm, o));
            float mn = fmaxf(m[q], cm);
            if (mn == -INFINITY) continue;

            float scale = expf(m[q] - mn);
            float p0 = expf(l0 - mn);
            float p1 = expf(l1 - mn);
            float psum = p0 + p1;
#pragma unroll
            for (int o = 16; o; o >>= 1) psum += __shfl_xor_sync(0xffffffffu, psum, o);
            l[q] = l[q] * scale + psum;
            o0[q] *= scale;
            o1[q] *= scale;
#pragma unroll
            for (int s2 = 0; s2 < 32; s2++) {
                float p = __shfl_sync(0xffffffffu, p0, s2);
                o0[q] = fmaf(p, Vs[s2][lane], o0[q]);
                o1[q] = fmaf(p, Vs[s2][lane + 32], o1[q]);
            }
#pragma unroll
            for (int s2 = 0; s2 < 32; s2++) {
                float p = __shfl_sync(0xffffffffu, p1, s2);
                o0[q] = fmaf(p, Vs[s2 + 32][lane], o0[q]);
                o1[q] = fmaf(p, Vs[s2 + 32][lane + 32], o1[q]);
            }
            m[q] = mn;
        }
        __syncthreads();
    }

#pragma unroll
    for (int q = 0; q < 4; q++) {
        int i = t0 + w * 4 + q;
        float inv = 1.f / l[q];
        float v0 = o0[q] * inv, v1 = o1[q] * inv;
        size_t base = (size_t)(b * TSZ + i) * KEXP + h * CSZ;
        __nv_bfloat16 h0 = __float2bfloat16(v0);
        __nv_bfloat16 lo0 = __float2bfloat16(v0 - __bfloat162float(h0));
        __nv_bfloat16 h1 = __float2bfloat16(v1);
        __nv_bfloat16 lo1 = __float2bfloat16(v1 - __bfloat162float(h1));
        g_attbf[base + lane]              = h0;
        g_attbf[base + 512 + lane]        = lo0;
        g_attbf[base + 1024 + lane]       = h0;
        g_attbf[base + lane + 32]         = h1;
        g_attbf[base + 512 + lane + 32]   = lo1;
        g_attbf[base + 1024 + lane + 32]  = h1;
    }
}

// ---------------------------------------------------------------------------
extern "C" void kernel_launch(void* const* d_in, const int* in_sizes, int n_in,
                              void* d_out, int out_size)
{
    const float* h        = (const float*)d_in[0];
    const float* rope_cos = (const float*)d_in[1];
    const float* rope_sin = (const float*)d_in[2];
    const float* W_q      = (const float*)d_in[3];
    const float* W_k      = (const float*)d_in[4];
    const float* W_v      = (const float*)d_in[5];
    const float* W_o      = (const float*)d_in[6];
    const float* q_norm_w = (const float*)d_in[7];
    const float* k_norm_w = (const float*)d_in[8];
    float* out = (float*)d_out;

    cudaFuncSetAttribute(qkv_mma, cudaFuncAttributeMaxDynamicSharedMemorySize, SMEM_BYTES);
    cudaFuncSetAttribute(out_mma, cudaFuncAttributeMaxDynamicSharedMemorySize, SMEM_BYTES);

    convert_h<<<(MROWS * DSZ) / 256, 256>>>(h);
    convert_w<<<dim3((512 * 512) / 256, 1, 4), 256>>>(W_q, W_k, W_v, W_o);

    qkv_mma<<<dim3(4, 32, 3), 256, SMEM_BYTES>>>();

    norm_rope<<<dim3(BSZ * TSZ * HSZ / 8, 2), 256>>>(rope_cos, rope_sin, q_norm_w, k_norm_w);

    attn_kernel<<<dim3(TSZ / 32, HSZ, BSZ), 256>>>();

    out_mma<<<dim3(4, 32, 1), 256, SMEM_BYTES>>>(out);
}

// round 10
// speedup vs baseline: 2.0684x; 1.2579x over previous
#include <cuda_runtime.h>
#include <cuda_bf16.h>
#include <math.h>
#include <stdint.h>

#define BSZ 2
#define TSZ 2048
#define DSZ 512
#define HSZ 8
#define CSZ 64
#define WINSZ 128
#define MROWS (BSZ*TSZ)   // 4096
#define KEXP 1536          // 3 * 512 (bf16 split: hi | lo | hi)
#define KC 64              // K per pipeline chunk
#define NCH (KEXP/KC)      // 24
#define STAGES 2
#define LDT 72             // padded smem row stride (bf16 elems); 144B rows
#define STAGE_ELEMS (128*LDT)               // 9216
#define SMEM_BYTES (2*STAGES*STAGE_ELEMS*2) // 73728

// ---------------------------------------------------------------------------
// Scratch (device globals: no allocation allowed)
// ---------------------------------------------------------------------------
__device__ float g_q[BSZ*TSZ*HSZ*CSZ];
__device__ float g_k[BSZ*TSZ*HSZ*CSZ];
__device__ float g_v[BSZ*TSZ*HSZ*CSZ];
__device__ __nv_bfloat16 g_Abf[MROWS*KEXP];     // split h
__device__ __nv_bfloat16 g_attbf[MROWS*KEXP];   // split attention output
__device__ __nv_bfloat16 g_Wqb[512*KEXP];
__device__ __nv_bfloat16 g_Wkb[512*KEXP];
__device__ __nv_bfloat16 g_Wvb[512*KEXP];
__device__ __nv_bfloat16 g_Wob[512*KEXP];

// ---------------------------------------------------------------------------
// PTX helpers (sm_80+ — compile on base sm_103 target)
// ---------------------------------------------------------------------------
__device__ __forceinline__ uint32_t smem_u32(const void* p) {
    uint32_t a;
    asm("{ .reg .u64 t; cvta.to.shared.u64 t, %1; cvt.u32.u64 %0, t; }" : "=r"(a) : "l"(p));
    return a;
}
__device__ __forceinline__ void cp16(uint32_t dst, const void* src) {
    asm volatile("cp.async.cg.shared.global [%0], [%1], 16;" :: "r"(dst), "l"(src));
}
#define CP_COMMIT() asm volatile("cp.async.commit_group;" ::: "memory")
#define CP_WAIT(n)  asm volatile("cp.async.wait_group %0;" :: "n"(n) : "memory")

__device__ __forceinline__ void ldm_x4(uint32_t& r0, uint32_t& r1,
                                       uint32_t& r2, uint32_t& r3, uint32_t addr) {
    asm volatile("ldmatrix.sync.aligned.m8n8.x4.shared.b16 {%0,%1,%2,%3}, [%4];"
                 : "=r"(r0), "=r"(r1), "=r"(r2), "=r"(r3) : "r"(addr));
}
__device__ __forceinline__ void mma16816(float* d, const uint32_t* a, const uint32_t* b) {
    asm volatile("mma.sync.aligned.m16n8k16.row.col.f32.bf16.bf16.f32 "
                 "{%0,%1,%2,%3}, {%4,%5,%6,%7}, {%8,%9}, {%0,%1,%2,%3};"
                 : "+f"(d[0]), "+f"(d[1]), "+f"(d[2]), "+f"(d[3])
                 : "r"(a[0]), "r"(a[1]), "r"(a[2]), "r"(a[3]), "r"(b[0]), "r"(b[1]));
}

// ---------------------------------------------------------------------------
// Split conversions: x -> (hi, lo, hi) / weights -> transposed (hi, hi, lo)
// ---------------------------------------------------------------------------
__global__ void __launch_bounds__(256)
convert_h(const float* __restrict__ h)
{
    int idx = blockIdx.x * 256 + threadIdx.x;       // 0 .. 4096*512-1
    int m = idx >> 9, k = idx & 511;
    float x = h[idx];
    __nv_bfloat16 hi = __float2bfloat16(x);
    __nv_bfloat16 lo = __float2bfloat16(x - __bfloat162float(hi));
    size_t base = (size_t)m * KEXP;
    g_Abf[base + k]        = hi;
    g_Abf[base + 512 + k]  = lo;
    g_Abf[base + 1024 + k] = hi;
}

__global__ void __launch_bounds__(256)
convert_w(const float* __restrict__ Wq, const float* __restrict__ Wk,
          const float* __restrict__ Wv, const float* __restrict__ Wo)
{
    const float* W = (blockIdx.z == 0) ? Wq : (blockIdx.z == 1) ? Wk
                   : (blockIdx.z == 2) ? Wv : Wo;
    __nv_bfloat16* Wb = (blockIdx.z == 0) ? g_Wqb : (blockIdx.z == 1) ? g_Wkb
                      : (blockIdx.z == 2) ? g_Wvb : g_Wob;
    int idx = blockIdx.x * 256 + threadIdx.x;       // 0 .. 512*512-1
    int k = idx >> 9, n = idx & 511;                 // W[k][n]
    float x = W[idx];
    __nv_bfloat16 hi = __float2bfloat16(x);
    __nv_bfloat16 lo = __float2bfloat16(x - __bfloat162float(hi));
    size_t base = (size_t)n * KEXP;
    Wb[base + k]        = hi;
    Wb[base + 512 + k]  = hi;
    Wb[base + 1024 + k] = lo;
}

// ---------------------------------------------------------------------------
// bf16 mma.sync GEMM with cp.async 2-stage pipeline, 2 CTAs/SM.
// C[128x128 tile] = A'[M,1536] @ B'[N,1536]^T, fp32 accum.
// 256 threads = 8 warps (4 along M x 2 along N); warp tile 32x64.
// ---------------------------------------------------------------------------
__device__ __forceinline__ void gemm_mma_body(const __nv_bfloat16* __restrict__ A,
                                              const __nv_bfloat16* __restrict__ Bw,
                                              float* __restrict__ C,
                                              __nv_bfloat16* sm)
{
    const int tid = threadIdx.x;
    const int lane = tid & 31, wid = tid >> 5;
    const int wm = (wid & 3) * 32;      // warp M offset
    const int wn = (wid >> 2) * 64;     // warp N offset
    const int m0 = blockIdx.y * 128, n0 = blockIdx.x * 128;

    const uint32_t smA = smem_u32(sm);
    const uint32_t smB = smA + STAGES * STAGE_ELEMS * 2;

    // cp.async mapping: 1024 16B-units per matrix per stage; 4 per thread.
    const __nv_bfloat16* gA = A  + (size_t)m0 * KEXP;
    const __nv_bfloat16* gB = Bw + (size_t)n0 * KEXP;

    auto load_stage = [&](int s, int c) {
        const int k0 = c * KC;
        const uint32_t dA = smA + s * STAGE_ELEMS * 2;
        const uint32_t dB = smB + s * STAGE_ELEMS * 2;
#pragma unroll
        for (int i = 0; i < 4; i++) {
            int u = i * 256 + tid;
            int row = u >> 3, seg = (u & 7) * 8;
            uint32_t so = (uint32_t)(row * LDT + seg) * 2;
            cp16(dA + so, gA + (size_t)row * KEXP + k0 + seg);
            cp16(dB + so, gB + (size_t)row * KEXP + k0 + seg);
        }
    };

    float acc[2][8][4];
#pragma unroll
    for (int mt = 0; mt < 2; mt++)
#pragma unroll
        for (int nt = 0; nt < 8; nt++)
#pragma unroll
            for (int r = 0; r < 4; r++) acc[mt][nt][r] = 0.f;

    // prologue: stage 0 only (2-stage pipeline)
    load_stage(0, 0); CP_COMMIT();

    const int a_ld = (wm + (lane & 15)) * LDT + (lane >> 4) * 8;
    const int b_ld = (wn + (lane & 15)) * LDT + (lane >> 4) * 8;

    for (int c = 0; c < NCH; c++) {
        CP_WAIT(0);            // only chunk c's load is outstanding here
        __syncthreads();

        // issue next chunk into the other buffer; overlaps with compute below
        if (c + 1 < NCH) { load_stage((c + 1) & 1, c + 1); CP_COMMIT(); }

        const int buf = c & 1;
        const uint32_t sa = smA + buf * STAGE_ELEMS * 2;
        const uint32_t sb = smB + buf * STAGE_ELEMS * 2;
#pragma unroll
        for (int ks = 0; ks < 4; ks++) {
            const int kk = ks * 16;
            uint32_t a[2][4];
#pragma unroll
            for (int mt = 0; mt < 2; mt++)
                ldm_x4(a[mt][0], a[mt][1], a[mt][2], a[mt][3],
                       sa + 2 * (a_ld + mt * 16 * LDT + kk));
            uint32_t b[8][2];
#pragma unroll
            for (int np = 0; np < 4; np++) {
                uint32_t r0, r1, r2, r3;
                ldm_x4(r0, r1, r2, r3, sb + 2 * (b_ld + np * 16 * LDT + kk));
                b[2*np][0] = r0; b[2*np][1] = r2;
                b[2*np+1][0] = r1; b[2*np+1][1] = r3;
            }
#pragma unroll
            for (int mt = 0; mt < 2; mt++)
#pragma unroll
                for (int nt = 0; nt < 8; nt++)
                    mma16816(acc[mt][nt], a[mt], b[nt]);
        }
        __syncthreads();   // all warps done with buf before it is refilled next iter
    }

    // epilogue: fragment -> global (row stride 512)
    const int gr = lane >> 2, gc = (lane & 3) * 2;
#pragma unroll
    for (int mt = 0; mt < 2; mt++)
#pragma unroll
        for (int nt = 0; nt < 8; nt++) {
            float* base = C + (size_t)(m0 + wm + mt * 16 + gr) * 512 + n0 + wn + nt * 8 + gc;
            *(float2*)base             = make_float2(acc[mt][nt][0], acc[mt][nt][1]);
            *(float2*)(base + 8 * 512) = make_float2(acc[mt][nt][2], acc[mt][nt][3]);
        }
}

__global__ void __launch_bounds__(256, 2)
qkv_mma()
{
    extern __shared__ __nv_bfloat16 sm[];
    const __nv_bfloat16* B = (blockIdx.z == 0) ? g_Wqb : (blockIdx.z == 1) ? g_Wkb : g_Wvb;
    float* C = (blockIdx.z == 0) ? g_q : (blockIdx.z == 1) ? g_k : g_v;
    gemm_mma_body(g_Abf, B, C, sm);
}

__global__ void __launch_bounds__(256, 2)
out_mma(float* __restrict__ out)
{
    extern __shared__ __nv_bfloat16 sm[];
    gemm_mma_body(g_attbf, g_Wob, out, sm);
}

// ---------------------------------------------------------------------------
// RMSNorm + RoPE (fp32 in place on g_q / g_k)
// ---------------------------------------------------------------------------
__global__ void __launch_bounds__(256)
norm_rope(const float* __restrict__ cosT, const float* __restrict__ sinT,
          const float* __restrict__ qw, const float* __restrict__ kw)
{
    int w = blockIdx.x * 8 + (threadIdx.x >> 5);
    int lane = threadIdx.x & 31;
    int t = (w / HSZ) % TSZ;

    float* x = ((blockIdx.y == 0) ? g_q : g_k) + (size_t)w * CSZ;
    const float* wgt = (blockIdx.y == 0) ? qw : kw;

    float x0 = x[lane];
    float x1 = x[lane + 32];
    float ss = x0 * x0 + x1 * x1;
#pragma unroll
    for (int o = 16; o; o >>= 1) ss += __shfl_xor_sync(0xffffffffu, ss, o);
    float nrm = rsqrtf(ss * (1.f / CSZ) + 1e-6f);
    float y0 = x0 * nrm * wgt[lane];
    float y1 = x1 * nrm * wgt[lane + 32];

    float c0 = cosT[t * CSZ + lane];
    float c1 = cosT[t * CSZ + lane + 32];
    float s0 = sinT[t * CSZ + lane];
    float s1 = sinT[t * CSZ + lane + 32];
    x[lane]      = y0 * c0 - y1 * s0;
    x[lane + 32] = y1 * c1 + y0 * s1;
}

// ---------------------------------------------------------------------------
// Sliding-window attention, vectorized smem (pad 68: 16B-aligned rows,
// conflict-free LDS.128/LDS.64). QK: key-per-lane; PV: channel-pair-per-lane.
// Epilogue writes bf16 split directly into g_attbf.
// ---------------------------------------------------------------------------
__global__ void __launch_bounds__(256)
attn_kernel()
{
    __shared__ float Qs[32][68];
    __shared__ float Ks[64][68];
    __shared__ float Vs[64][68];

    const int b = blockIdx.z, h = blockIdx.y;
    const int t0 = blockIdx.x * 32;
    const int tid = threadIdx.x;
    const int lane = tid & 31;
    const int w = tid >> 5;

    for (int idx = tid; idx < 32 * 16; idx += 256) {
        int r = idx >> 4, c4 = (idx & 15) * 4;
        float4 v = *(const float4*)&g_q[(((size_t)(b * TSZ + t0 + r) * HSZ) + h) * CSZ + c4];
        *(float4*)&Qs[r][c4] = v;
    }

    float m[4], l[4];
    float2 o[4];
#pragma unroll
    for (int q = 0; q < 4; q++) { m[q] = -INFINITY; l[q] = 0.f; o[q] = make_float2(0.f, 0.f); }

    for (int ch = 0; ch < 3; ch++) {
        int s_base = t0 - 128 + ch * 64;
        for (int idx = tid; idx < 64 * 16; idx += 256) {
            int r = idx >> 4, c4 = (idx & 15) * 4;
            int s = s_base + r;
            float4 kv = make_float4(0.f, 0.f, 0.f, 0.f), vv = kv;
            if (s >= 0 && s < TSZ) {
                size_t base = (((size_t)(b * TSZ + s) * HSZ) + h) * CSZ + c4;
                kv = *(const float4*)&g_k[base];
                vv = *(const float4*)&g_v[base];
            }
            *(float4*)&Ks[r][c4] = kv;
            *(float4*)&Vs[r][c4] = vv;
        }
        __syncthreads();

#pragma unroll
        for (int q = 0; q < 4; q++) {
            const int qi = w * 4 + q;
            const int i = t0 + qi;
            float acc0 = 0.f, acc1 = 0.f;
#pragma unroll
            for (int c4 = 0; c4 < 64; c4 += 4) {
                float4 qv = *(const float4*)&Qs[qi][c4];
                float4 ka = *(const float4*)&Ks[lane][c4];
                float4 kb = *(const float4*)&Ks[lane + 32][c4];
                acc0 = fmaf(qv.x, ka.x, acc0); acc0 = fmaf(qv.y, ka.y, acc0);
                acc0 = fmaf(qv.z, ka.z, acc0); acc0 = fmaf(qv.w, ka.w, acc0);
                acc1 = fmaf(qv.x, kb.x, acc1); acc1 = fmaf(qv.y, kb.y, acc1);
                acc1 = fmaf(qv.z, kb.z, acc1); acc1 = fmaf(qv.w, kb.w, acc1);
            }
            int s0g = s_base + lane, s1g = s_base + lane + 32;
            float l0 = (s0g >= 0 && s0g <= i && s0g > i - WINSZ) ? acc0 * 0.125f : -INFINITY;
            float l1 = (s1g >= 0 && s1g <= i && s1g > i - WINSZ) ? acc1 * 0.125f : -INFINITY;
            float cm = fmaxf(l0, l1);
#pragma unroll
            for (int off = 16; off; off >>= 1) cm = fmaxf(cm, __shfl_xor_sync(0xffffffffu, cm, off));
            float mn = fmaxf(m[q], cm);
            if (mn == -INFINITY) continue;   // warp-uniform: chunk fully masked

            float scale = expf(m[q] - mn);
            float p0 = expf(l0 - mn);
            float p1 = expf(l1 - mn);
            float psum = p0 + p1;
#pragma unroll
            for (int off = 16; off; off >>= 1) psum += __shfl_xor_sync(0xffffffffu, psum, off);
            l[q] = l[q] * scale + psum;
            o[q].x *= scale;
            o[q].y *= scale;
            // PV: lane owns channels (2*lane, 2*lane+1)
#pragma unroll
            for (int s2 = 0; s2 < 32; s2++) {
                float p = __shfl_sync(0xffffffffu, p0, s2);
                float2 vv = *(const float2*)&Vs[s2][2 * lane];
                o[q].x = fmaf(p, vv.x, o[q].x);
                o[q].y = fmaf(p, vv.y, o[q].y);
            }
#pragma unroll
            for (int s2 = 0; s2 < 32; s2++) {
                float p = __shfl_sync(0xffffffffu, p1, s2);
                float2 vv = *(const float2*)&Vs[s2 + 32][2 * lane];
                o[q].x = fmaf(p, vv.x, o[q].x);
                o[q].y = fmaf(p, vv.y, o[q].y);
            }
            m[q] = mn;
        }
        __syncthreads();
    }

#pragma unroll
    for (int q = 0; q < 4; q++) {
        int i = t0 + w * 4 + q;
        float inv = 1.f / l[q];
        float v0 = o[q].x * inv, v1 = o[q].y * inv;
        int c0 = 2 * lane, c1 = 2 * lane + 1;
        size_t base = (size_t)(b * TSZ + i) * KEXP + h * CSZ;
        __nv_bfloat16 h0 = __float2bfloat16(v0);
        __nv_bfloat16 lo0 = __float2bfloat16(v0 - __bfloat162float(h0));
        __nv_bfloat16 h1 = __float2bfloat16(v1);
        __nv_bfloat16 lo1 = __float2bfloat16(v1 - __bfloat162float(h1));
        g_attbf[base + c0]         = h0;
        g_attbf[base + 512 + c0]   = lo0;
        g_attbf[base + 1024 + c0]  = h0;
        g_attbf[base + c1]         = h1;
        g_attbf[base + 512 + c1]   = lo1;
        g_attbf[base + 1024 + c1]  = h1;
    }
}

// ---------------------------------------------------------------------------
extern "C" void kernel_launch(void* const* d_in, const int* in_sizes, int n_in,
                              void* d_out, int out_size)
{
    const float* h        = (const float*)d_in[0];
    const float* rope_cos = (const float*)d_in[1];
    const float* rope_sin = (const float*)d_in[2];
    const float* W_q      = (const float*)d_in[3];
    const float* W_k      = (const float*)d_in[4];
    const float* W_v      = (const float*)d_in[5];
    const float* W_o      = (const float*)d_in[6];
    const float* q_norm_w = (const float*)d_in[7];
    const float* k_norm_w = (const float*)d_in[8];
    float* out = (float*)d_out;

    cudaFuncSetAttribute(qkv_mma, cudaFuncAttributeMaxDynamicSharedMemorySize, SMEM_BYTES);
    cudaFuncSetAttribute(out_mma, cudaFuncAttributeMaxDynamicSharedMemorySize, SMEM_BYTES);

    convert_h<<<(MROWS * DSZ) / 256, 256>>>(h);
    convert_w<<<dim3((512 * 512) / 256, 1, 4), 256>>>(W_q, W_k, W_v, W_o);

    qkv_mma<<<dim3(4, 32, 3), 256, SMEM_BYTES>>>();

    norm_rope<<<dim3(BSZ * TSZ * HSZ / 8, 2), 256>>>(rope_cos, rope_sin, q_norm_w, k_norm_w);

    attn_kernel<<<dim3(TSZ / 32, HSZ, BSZ), 256>>>();

    out_mma<<<dim3(4, 32, 1), 256, SMEM_BYTES>>>(out);
}

// round 13
// speedup vs baseline: 2.1673x; 1.0478x over previous
#include <cuda_runtime.h>
#include <cuda_bf16.h>
#include <math.h>
#include <stdint.h>

#define BSZ 2
#define TSZ 2048
#define DSZ 512
#define HSZ 8
#define CSZ 64
#define WINSZ 128
#define MROWS (BSZ*TSZ)   // 4096
#define KSTORE 1024        // stored K: [hi(512) | lo(512)]
#define KC 64              // K per pipeline chunk
#define NCH 24             // 3 passes x 8 chunks (AhBh, AlBh, AhBl)
#define STAGES 3
#define LDT 72             // padded smem row stride (bf16 elems); 144B rows
#define STAGE_ELEMS (128*LDT)               // 9216
#define SMEM_BYTES (2*STAGES*STAGE_ELEMS*2) // 110592

// ---------------------------------------------------------------------------
// Scratch (device globals: no allocation allowed)
// ---------------------------------------------------------------------------
__device__ float g_q[BSZ*TSZ*HSZ*CSZ];
__device__ float g_k[BSZ*TSZ*HSZ*CSZ];
__device__ float g_v[BSZ*TSZ*HSZ*CSZ];
__device__ __nv_bfloat16 g_Abf[MROWS*KSTORE];    // split h [hi|lo]
__device__ __nv_bfloat16 g_attbf[MROWS*KSTORE];  // split attention output [hi|lo]
__device__ __nv_bfloat16 g_Wqb[512*KSTORE];
__device__ __nv_bfloat16 g_Wkb[512*KSTORE];
__device__ __nv_bfloat16 g_Wvb[512*KSTORE];
__device__ __nv_bfloat16 g_Wob[512*KSTORE];

// ---------------------------------------------------------------------------
// PTX helpers (sm_80+ — compile on base sm_103 target)
// ---------------------------------------------------------------------------
__device__ __forceinline__ uint32_t smem_u32(const void* p) {
    uint32_t a;
    asm("{ .reg .u64 t; cvta.to.shared.u64 t, %1; cvt.u32.u64 %0, t; }" : "=r"(a) : "l"(p));
    return a;
}
__device__ __forceinline__ void cp16(uint32_t dst, const void* src) {
    asm volatile("cp.async.cg.shared.global [%0], [%1], 16;" :: "r"(dst), "l"(src));
}
#define CP_COMMIT() asm volatile("cp.async.commit_group;" ::: "memory")
#define CP_WAIT(n)  asm volatile("cp.async.wait_group %0;" :: "n"(n) : "memory")

__device__ __forceinline__ void ldm_x4(uint32_t& r0, uint32_t& r1,
                                       uint32_t& r2, uint32_t& r3, uint32_t addr) {
    asm volatile("ldmatrix.sync.aligned.m8n8.x4.shared.b16 {%0,%1,%2,%3}, [%4];"
                 : "=r"(r0), "=r"(r1), "=r"(r2), "=r"(r3) : "r"(addr));
}
__device__ __forceinline__ void mma16816(float* d, const uint32_t* a, const uint32_t* b) {
    asm volatile("mma.sync.aligned.m16n8k16.row.col.f32.bf16.bf16.f32 "
                 "{%0,%1,%2,%3}, {%4,%5,%6,%7}, {%8,%9}, {%0,%1,%2,%3};"
                 : "+f"(d[0]), "+f"(d[1]), "+f"(d[2]), "+f"(d[3])
                 : "r"(a[0]), "r"(a[1]), "r"(a[2]), "r"(a[3]), "r"(b[0]), "r"(b[1]));
}

// per-chunk K offsets into [hi|lo] storage:
// c 0..7  : A hi, B hi   c 8..15 : A lo, B hi   c 16..23: A hi, B lo
__device__ __forceinline__ int k0A(int c) {
    return ((c >> 3) == 1 ? 512 : 0) + (c & 7) * KC;
}
__device__ __forceinline__ int k0B(int c) {
    return ((c >> 3) == 2 ? 512 : 0) + (c & 7) * KC;
}

// ---------------------------------------------------------------------------
// Split conversions: x -> [hi | lo]; weights transposed -> [hi | lo]
// ---------------------------------------------------------------------------
__global__ void __launch_bounds__(256)
convert_h(const float* __restrict__ h)
{
    int idx = blockIdx.x * 256 + threadIdx.x;       // 0 .. 4096*512-1
    int m = idx >> 9, k = idx & 511;
    float x = h[idx];
    __nv_bfloat16 hi = __float2bfloat16(x);
    __nv_bfloat16 lo = __float2bfloat16(x - __bfloat162float(hi));
    size_t base = (size_t)m * KSTORE;
    g_Abf[base + k]       = hi;
    g_Abf[base + 512 + k] = lo;
}

__global__ void __launch_bounds__(256)
convert_w(const float* __restrict__ Wq, const float* __restrict__ Wk,
          const float* __restrict__ Wv, const float* __restrict__ Wo)
{
    const float* W = (blockIdx.z == 0) ? Wq : (blockIdx.z == 1) ? Wk
                   : (blockIdx.z == 2) ? Wv : Wo;
    __nv_bfloat16* Wb = (blockIdx.z == 0) ? g_Wqb : (blockIdx.z == 1) ? g_Wkb
                      : (blockIdx.z == 2) ? g_Wvb : g_Wob;
    int idx = blockIdx.x * 256 + threadIdx.x;       // 0 .. 512*512-1
    int k = idx >> 9, n = idx & 511;                 // W[k][n]
    float x = W[idx];
    __nv_bfloat16 hi = __float2bfloat16(x);
    __nv_bfloat16 lo = __float2bfloat16(x - __bfloat162float(hi));
    size_t base = (size_t)n * KSTORE;
    Wb[base + k]       = hi;
    Wb[base + 512 + k] = lo;
}

// ---------------------------------------------------------------------------
// bf16 mma.sync GEMM, cp.async 3-stage pipeline, 2 CTAs/SM, 1 barrier/chunk.
// C[128x128 tile] = sum over 24 chunks of A[.,k0A]·B[.,k0B]^T, fp32 accum.
// 256 threads = 8 warps (4 along M x 2 along N); warp tile 32x64.
// ---------------------------------------------------------------------------
__device__ __forceinline__ void gemm_mma_body(const __nv_bfloat16* __restrict__ A,
                                              const __nv_bfloat16* __restrict__ Bw,
                                              float* __restrict__ C,
                                              __nv_bfloat16* sm)
{
    const int tid = threadIdx.x;
    const int lane = tid & 31, wid = tid >> 5;
    const int wm = (wid & 3) * 32;      // warp M offset
    const int wn = (wid >> 2) * 64;     // warp N offset
    const int m0 = blockIdx.y * 128, n0 = blockIdx.x * 128;

    const uint32_t smA = smem_u32(sm);
    const uint32_t smB = smA + STAGES * STAGE_ELEMS * 2;

    const __nv_bfloat16* gA = A  + (size_t)m0 * KSTORE;
    const __nv_bfloat16* gB = Bw + (size_t)n0 * KSTORE;

    // cp.async mapping: 1024 16B-units per matrix per stage; 4 per thread.
    auto load_stage = [&](int s, int c) {
        const int kA = k0A(c), kB = k0B(c);
        const uint32_t dA = smA + s * STAGE_ELEMS * 2;
        const uint32_t dB = smB + s * STAGE_ELEMS * 2;
#pragma unroll
        for (int i = 0; i < 4; i++) {
            int u = i * 256 + tid;
            int row = u >> 3, seg = (u & 7) * 8;
            uint32_t so = (uint32_t)(row * LDT + seg) * 2;
            cp16(dA + so, gA + (size_t)row * KSTORE + kA + seg);
            cp16(dB + so, gB + (size_t)row * KSTORE + kB + seg);
        }
    };

    float acc[2][8][4];
#pragma unroll
    for (int mt = 0; mt < 2; mt++)
#pragma unroll
        for (int nt = 0; nt < 8; nt++)
#pragma unroll
            for (int r = 0; r < 4; r++) acc[mt][nt][r] = 0.f;

    // prologue: stages 0 and 1
    load_stage(0, 0); CP_COMMIT();
    load_stage(1, 1); CP_COMMIT();

    const int a_ld = (wm + (lane & 15)) * LDT + (lane >> 4) * 8;
    const int b_ld = (wn + (lane & 15)) * LDT + (lane >> 4) * 8;

    for (int c = 0; c < NCH; c++) {
        CP_WAIT(1);            // chunk c resident (chunk c+1 may be in flight)
        __syncthreads();       // all warps past compute of c-1 (buffer (c+2)%3)

        if (c + 2 < NCH) load_stage((c + 2) % STAGES, c + 2);
        CP_COMMIT();           // always commit (keeps group accounting aligned)

        const int buf = c % STAGES;
        const uint32_t sa = smA + buf * STAGE_ELEMS * 2;
        const uint32_t sb = smB + buf * STAGE_ELEMS * 2;
#pragma unroll
        for (int ks = 0; ks < 4; ks++) {
            const int kk = ks * 16;
            uint32_t a[2][4];
#pragma unroll
            for (int mt = 0; mt < 2; mt++)
                ldm_x4(a[mt][0], a[mt][1], a[mt][2], a[mt][3],
                       sa + 2 * (a_ld + mt * 16 * LDT + kk));
            uint32_t b[8][2];
#pragma unroll
            for (int np = 0; np < 4; np++) {
                uint32_t r0, r1, r2, r3;
                ldm_x4(r0, r1, r2, r3, sb + 2 * (b_ld + np * 16 * LDT + kk));
                b[2*np][0] = r0; b[2*np][1] = r2;
                b[2*np+1][0] = r1; b[2*np+1][1] = r3;
            }
#pragma unroll
            for (int mt = 0; mt < 2; mt++)
#pragma unroll
                for (int nt = 0; nt < 8; nt++)
                    mma16816(acc[mt][nt], a[mt], b[nt]);
        }
    }

    // epilogue: fragment -> global (row stride 512)
    const int gr = lane >> 2, gc = (lane & 3) * 2;
#pragma unroll
    for (int mt = 0; mt < 2; mt++)
#pragma unroll
        for (int nt = 0; nt < 8; nt++) {
            float* base = C + (size_t)(m0 + wm + mt * 16 + gr) * 512 + n0 + wn + nt * 8 + gc;
            *(float2*)base             = make_float2(acc[mt][nt][0], acc[mt][nt][1]);
            *(float2*)(base + 8 * 512) = make_float2(acc[mt][nt][2], acc[mt][nt][3]);
        }
}

__global__ void __launch_bounds__(256, 2)
qkv_mma()
{
    extern __shared__ __nv_bfloat16 sm[];
    const __nv_bfloat16* B = (blockIdx.z == 0) ? g_Wqb : (blockIdx.z == 1) ? g_Wkb : g_Wvb;
    float* C = (blockIdx.z == 0) ? g_q : (blockIdx.z == 1) ? g_k : g_v;
    gemm_mma_body(g_Abf, B, C, sm);
}

__global__ void __launch_bounds__(256, 2)
out_mma(float* __restrict__ out)
{
    extern __shared__ __nv_bfloat16 sm[];
    gemm_mma_body(g_attbf, g_Wob, out, sm);
}

// ---------------------------------------------------------------------------
// RMSNorm + RoPE (fp32 in place on g_q / g_k)
// ---------------------------------------------------------------------------
__global__ void __launch_bounds__(256)
norm_rope(const float* __restrict__ cosT, const float* __restrict__ sinT,
          const float* __restrict__ qw, const float* __restrict__ kw)
{
    int w = blockIdx.x * 8 + (threadIdx.x >> 5);
    int lane = threadIdx.x & 31;
    int t = (w / HSZ) % TSZ;

    float* x = ((blockIdx.y == 0) ? g_q : g_k) + (size_t)w * CSZ;
    const float* wgt = (blockIdx.y == 0) ? qw : kw;

    float x0 = x[lane];
    float x1 = x[lane + 32];
    float ss = x0 * x0 + x1 * x1;
#pragma unroll
    for (int o = 16; o; o >>= 1) ss += __shfl_xor_sync(0xffffffffu, ss, o);
    float nrm = rsqrtf(ss * (1.f / CSZ) + 1e-6f);
    float y0 = x0 * nrm * wgt[lane];
    float y1 = x1 * nrm * wgt[lane + 32];

    float c0 = cosT[t * CSZ + lane];
    float c1 = cosT[t * CSZ + lane + 32];
    float s0 = sinT[t * CSZ + lane];
    float s1 = sinT[t * CSZ + lane + 32];
    x[lane]      = y0 * c0 - y1 * s0;
    x[lane + 32] = y1 * c1 + y0 * s1;
}

// ---------------------------------------------------------------------------
// Sliding-window attention, vectorized smem (pad 68: 16B-aligned rows,
// conflict-free LDS.128/LDS.64). QK: key-per-lane; PV: channel-pair-per-lane.
// Epilogue writes bf16 [hi|lo] split directly into g_attbf.
// ---------------------------------------------------------------------------
__global__ void __launch_bounds__(256)
attn_kernel()
{
    __shared__ float Qs[32][68];
    __shared__ float Ks[64][68];
    __shared__ float Vs[64][68];

    const int b = blockIdx.z, h = blockIdx.y;
    const int t0 = blockIdx.x * 32;
    const int tid = threadIdx.x;
    const int lane = tid & 31;
    const int w = tid >> 5;

    for (int idx = tid; idx < 32 * 16; idx += 256) {
        int r = idx >> 4, c4 = (idx & 15) * 4;
        float4 v = *(const float4*)&g_q[(((size_t)(b * TSZ + t0 + r) * HSZ) + h) * CSZ + c4];
        *(float4*)&Qs[r][c4] = v;
    }

    float m[4], l[4];
    float2 o[4];
#pragma unroll
    for (int q = 0; q < 4; q++) { m[q] = -INFINITY; l[q] = 0.f; o[q] = make_float2(0.f, 0.f); }

    for (int ch = 0; ch < 3; ch++) {
        int s_base = t0 - 128 + ch * 64;
        for (int idx = tid; idx < 64 * 16; idx += 256) {
            int r = idx >> 4, c4 = (idx & 15) * 4;
            int s = s_base + r;
            float4 kv = make_float4(0.f, 0.f, 0.f, 0.f), vv = kv;
            if (s >= 0 && s < TSZ) {
                size_t base = (((size_t)(b * TSZ + s) * HSZ) + h) * CSZ + c4;
                kv = *(const float4*)&g_k[base];
                vv = *(const float4*)&g_v[base];
            }
            *(float4*)&Ks[r][c4] = kv;
            *(float4*)&Vs[r][c4] = vv;
        }
        __syncthreads();

#pragma unroll
        for (int q = 0; q < 4; q++) {
            const int qi = w * 4 + q;
            const int i = t0 + qi;
            float acc0 = 0.f, acc1 = 0.f;
#pragma unroll
            for (int c4 = 0; c4 < 64; c4 += 4) {
                float4 qv = *(const float4*)&Qs[qi][c4];
                float4 ka = *(const float4*)&Ks[lane][c4];
                float4 kb = *(const float4*)&Ks[lane + 32][c4];
                acc0 = fmaf(qv.x, ka.x, acc0); acc0 = fmaf(qv.y, ka.y, acc0);
                acc0 = fmaf(qv.z, ka.z, acc0); acc0 = fmaf(qv.w, ka.w, acc0);
                acc1 = fmaf(qv.x, kb.x, acc1); acc1 = fmaf(qv.y, kb.y, acc1);
                acc1 = fmaf(qv.z, kb.z, acc1); acc1 = fmaf(qv.w, kb.w, acc1);
            }
            int s0g = s_base + lane, s1g = s_base + lane + 32;
            float l0 = (s0g >= 0 && s0g <= i && s0g > i - WINSZ) ? acc0 * 0.125f : -INFINITY;
            float l1 = (s1g >= 0 && s1g <= i && s1g > i - WINSZ) ? acc1 * 0.125f : -INFINITY;
            float cm = fmaxf(l0, l1);
#pragma unroll
            for (int off = 16; off; off >>= 1) cm = fmaxf(cm, __shfl_xor_sync(0xffffffffu, cm, off));
            float mn = fmaxf(m[q], cm);
            if (mn == -INFINITY) continue;   // warp-uniform: chunk fully masked

            float scale = expf(m[q] - mn);
            float p0 = expf(l0 - mn);
            float p1 = expf(l1 - mn);
            float psum = p0 + p1;
#pragma unroll
            for (int off = 16; off; off >>= 1) psum += __shfl_xor_sync(0xffffffffu, psum, off);
            l[q] = l[q] * scale + psum;
            o[q].x *= scale;
            o[q].y *= scale;
            // PV: lane owns channels (2*lane, 2*lane+1)
#pragma unroll
            for (int s2 = 0; s2 < 32; s2++) {
                float p = __shfl_sync(0xffffffffu, p0, s2);
                float2 vv = *(const float2*)&Vs[s2][2 * lane];
                o[q].x = fmaf(p, vv.x, o[q].x);
                o[q].y = fmaf(p, vv.y, o[q].y);
            }
#pragma unroll
            for (int s2 = 0; s2 < 32; s2++) {
                float p = __shfl_sync(0xffffffffu, p1, s2);
                float2 vv = *(const float2*)&Vs[s2 + 32][2 * lane];
                o[q].x = fmaf(p, vv.x, o[q].x);
                o[q].y = fmaf(p, vv.y, o[q].y);
            }
            m[q] = mn;
        }
        __syncthreads();
    }

#pragma unroll
    for (int q = 0; q < 4; q++) {
        int i = t0 + w * 4 + q;
        float inv = 1.f / l[q];
        float v0 = o[q].x * inv, v1 = o[q].y * inv;
        int c0 = 2 * lane, c1 = 2 * lane + 1;
        size_t base = (size_t)(b * TSZ + i) * KSTORE + h * CSZ;
        __nv_bfloat16 h0 = __float2bfloat16(v0);
        __nv_bfloat16 lo0 = __float2bfloat16(v0 - __bfloat162float(h0));
        __nv_bfloat16 h1 = __float2bfloat16(v1);
        __nv_bfloat16 lo1 = __float2bfloat16(v1 - __bfloat162float(h1));
        g_attbf[base + c0]       = h0;
        g_attbf[base + 512 + c0] = lo0;
        g_attbf[base + c1]       = h1;
        g_attbf[base + 512 + c1] = lo1;
    }
}

// ---------------------------------------------------------------------------
extern "C" void kernel_launch(void* const* d_in, const int* in_sizes, int n_in,
                              void* d_out, int out_size)
{
    const float* h        = (const float*)d_in[0];
    const float* rope_cos = (const float*)d_in[1];
    const float* rope_sin = (const float*)d_in[2];
    const float* W_q      = (const float*)d_in[3];
    const float* W_k      = (const float*)d_in[4];
    const float* W_v      = (const float*)d_in[5];
    const float* W_o      = (const float*)d_in[6];
    const float* q_norm_w = (const float*)d_in[7];
    const float* k_norm_w = (const float*)d_in[8];
    float* out = (float*)d_out;

    cudaFuncSetAttribute(qkv_mma, cudaFuncAttributeMaxDynamicSharedMemorySize, SMEM_BYTES);
    cudaFuncSetAttribute(out_mma, cudaFuncAttributeMaxDynamicSharedMemorySize, SMEM_BYTES);

    convert_h<<<(MROWS * DSZ) / 256, 256>>>(h);
    convert_w<<<dim3((512 * 512) / 256, 1, 4), 256>>>(W_q, W_k, W_v, W_o);

    qkv_mma<<<dim3(4, 32, 3), 256, SMEM_BYTES>>>();

    norm_rope<<<dim3(BSZ * TSZ * HSZ / 8, 2), 256>>>(rope_cos, rope_sin, q_norm_w, k_norm_w);

    attn_kernel<<<dim3(TSZ / 32, HSZ, BSZ), 256>>>();

    out_mma<<<dim3(4, 32, 1), 256, SMEM_BYTES>>>(out);
}